// round 12
// baseline (speedup 1.0000x reference)
#include <cuda_runtime.h>
#include <cstddef>

// 2-layer tanh RNN (B=2048,T=512,I=8,H=64)+FC.
// R11: k-split-4 (12 SHFL.32/step), XOR-swizzled h layout (imm addressing,
// conflict-free), weights in registers (96), 1 barrier/step, grid 128 = 1 wave.
// lane = b(2) | kg(2)<<2 | e(1)<<4 ; thread = 2 rows x 16k x 4 chunks.

#define TT 512
typedef unsigned long long u64;

static __device__ __forceinline__ void fma2(u64& a, u64 u, u64 v) {
    asm("fma.rn.f32x2 %0, %1, %2, %0;" : "+l"(a) : "l"(u), "l"(v));
}
static __device__ __forceinline__ u64 mul2(u64 u, u64 v) {
    u64 r; asm("mul.rn.f32x2 %0, %1, %2;" : "=l"(r) : "l"(u), "l"(v)); return r;
}
static __device__ __forceinline__ u64 add2(u64 a, u64 b) {
    u64 r; asm("add.rn.f32x2 %0, %1, %2;" : "=l"(r) : "l"(a), "l"(b)); return r;
}
static __device__ __forceinline__ u64 pack2(float a, float b) {
    u64 r; asm("mov.b64 %0, {%1, %2};" : "=l"(r) : "f"(a), "f"(b)); return r;
}
static __device__ __forceinline__ void unpack2(u64 v, float& a, float& b) {
    asm("mov.b64 {%0, %1}, %2;" : "=f"(a), "=f"(b) : "l"(v));
}
static __device__ __forceinline__ float ftanh(float s) {
    const float e = __expf(2.0f * s);
    return 1.0f - __fdividef(2.0f, e + 1.0f);
}
static __device__ __forceinline__ u64 shx(u64 v, int m) {
    return __shfl_xor_sync(0xffffffffu, v, m, 32);
}
static __device__ __forceinline__ u64 foldp(u64 a, u64 b) {
    float l0, m0, l1, m1;
    unpack2(a, l0, m0); unpack2(b, l1, m1);
    return pack2(l0 + m0, l1 + m1);
}

__global__ void __launch_bounds__(512, 1)
rnn_main(const float* __restrict__ x,
         const float* __restrict__ Wih0, const float* __restrict__ Whh0,
         const float* __restrict__ bi0,  const float* __restrict__ bh0,
         const float* __restrict__ Wih1, const float* __restrict__ Whh1,
         const float* __restrict__ bi1,  const float* __restrict__ bh1,
         const float* __restrict__ fcw,  const float* __restrict__ fcb,
         float* __restrict__ out)
{
    // hs[layer][parity][batch*64 + slot*4 + pos]; slot = quad ^ (batch&3)
    __shared__ __align__(16) float hs[2][2][16 * 64];
    __shared__ __align__(8)  float bsm[2][64];

    const int tid  = threadIdx.x;
    const int lane = tid & 31;
    const int w    = tid >> 5;            // warp rows w*4 .. w*4+3
    const int b    = lane & 3;
    const int kg   = (lane >> 2) & 3;     // k in [16kg, 16kg+16)
    const int e    = lane >> 4;           // row-pair select
    const int jA   = w * 4 + 2 * e;       // owned rows jA, jA+1

    for (int i = tid; i < 16 * 64; i += 512) { hs[0][1][i] = 0.f; hs[1][1][i] = 0.f; }
    if (tid < 64) {
        bsm[0][tid] = bi0[tid] + bh0[tid];
        bsm[1][tid] = bi1[tid] + bh1[tid];
    }

    // chunk-slot bases (chunk(slot c) = c ^ kg; batch = chunk*4 + b)
    int hb[4], xo[4];
#pragma unroll
    for (int c = 0; c < 4; c++) {
        hb[c] = ((c ^ kg) * 4 + b) * 64 + 16 * kg;     // contiguous 16-float slice
        xo[c] = ((c ^ kg) * 4) * (TT * 8);             // float offset
    }
    const int sto = (kg * 4 + b) * 64 + ((w ^ b) << 2) + 2 * e;
    const float* xbase = x + ((size_t)(blockIdx.x * 16 + b) * TT) * 8 + 2 * kg;

    // Weights in registers; slot m holds logical k-quad 16kg/4 + (m ^ b).
    u64 wa[2][8], wb[2][8], wc[2][8], wx[2];
#pragma unroll
    for (int r = 0; r < 2; r++) {
        const int row = jA + r;
#pragma unroll
        for (int m = 0; m < 4; m++) {
            const int Lq = 4 * kg + (m ^ b);
#pragma unroll
            for (int u = 0; u < 2; u++) {
                const int idx = (row * 64 + Lq * 4) / 2 + u;
                wa[r][m * 2 + u] = reinterpret_cast<const u64*>(Whh0)[idx];
                wb[r][m * 2 + u] = reinterpret_cast<const u64*>(Wih1)[idx];
                wc[r][m * 2 + u] = reinterpret_cast<const u64*>(Whh1)[idx];
            }
        }
        wx[r] = reinterpret_cast<const u64*>(Wih0)[row * 4 + kg];  // i = 2kg,2kg+1
    }

    __syncthreads();

#define STEP(P, PQ, TCUR)                                                     \
    {                                                                         \
        u64 xq[4];                                                            \
        _Pragma("unroll")                                                     \
        for (int c = 0; c < 4; c++)                                           \
            xq[c] = *reinterpret_cast<const u64*>(xbase + xo[c] + (TCUR) * 8);\
        const u64 bz0 = *reinterpret_cast<const u64*>(&bsm[0][jA]);           \
        const u64 bz1 = *reinterpret_cast<const u64*>(&bsm[1][jA]);           \
        /* ---- layer 0 ---- */                                               \
        u64 pp[4];                                                            \
        _Pragma("unroll")                                                     \
        for (int c = 0; c < 4; c++) {                                         \
            const ulonglong2* hp =                                            \
                reinterpret_cast<const ulonglong2*>(&hs[0][PQ][hb[c]]);       \
            const ulonglong2 A = hp[0], Bq = hp[1], C = hp[2], D = hp[3];     \
            u64 r0 = mul2(wa[0][0], A.x),  r1 = mul2(wa[1][0], A.x);          \
            fma2(r0, wa[0][1], A.y);  fma2(r1, wa[1][1], A.y);                \
            fma2(r0, wa[0][2], Bq.x); fma2(r1, wa[1][2], Bq.x);               \
            fma2(r0, wa[0][3], Bq.y); fma2(r1, wa[1][3], Bq.y);               \
            fma2(r0, wa[0][4], C.x);  fma2(r1, wa[1][4], C.x);                \
            fma2(r0, wa[0][5], C.y);  fma2(r1, wa[1][5], C.y);                \
            fma2(r0, wa[0][6], D.x);  fma2(r1, wa[1][6], D.x);                \
            fma2(r0, wa[0][7], D.y);  fma2(r1, wa[1][7], D.y);                \
            fma2(r0, wx[0], xq[c]);   fma2(r1, wx[1], xq[c]);                 \
            pp[c] = foldp(r0, r1);                                            \
        }                                                                     \
        {                                                                     \
            u64 v0 = add2(pp[0], shx(pp[1], 4));                              \
            u64 v1 = add2(pp[2], shx(pp[3], 4));                              \
            u64 r  = add2(v0, shx(v1, 8));                                    \
            r = add2(r, bz0);                                                 \
            float f0, f1; unpack2(r, f0, f1);                                 \
            *reinterpret_cast<u64*>(&hs[0][P][sto]) =                         \
                pack2(ftanh(f0), ftanh(f1));                                  \
        }                                                                     \
        __syncthreads();                                                      \
        /* ---- layer 1 ---- */                                               \
        _Pragma("unroll")                                                     \
        for (int c = 0; c < 4; c++) {                                         \
            const ulonglong2* g0 =                                            \
                reinterpret_cast<const ulonglong2*>(&hs[0][P][hb[c]]);        \
            const ulonglong2 A = g0[0], Bq = g0[1], C = g0[2], D = g0[3];     \
            u64 r0 = mul2(wb[0][0], A.x),  r1 = mul2(wb[1][0], A.x);          \
            fma2(r0, wb[0][1], A.y);  fma2(r1, wb[1][1], A.y);                \
            fma2(r0, wb[0][2], Bq.x); fma2(r1, wb[1][2], Bq.x);               \
            fma2(r0, wb[0][3], Bq.y); fma2(r1, wb[1][3], Bq.y);               \
            fma2(r0, wb[0][4], C.x);  fma2(r1, wb[1][4], C.x);                \
            fma2(r0, wb[0][5], C.y);  fma2(r1, wb[1][5], C.y);                \
            fma2(r0, wb[0][6], D.x);  fma2(r1, wb[1][6], D.x);                \
            fma2(r0, wb[0][7], D.y);  fma2(r1, wb[1][7], D.y);                \
            const ulonglong2* g1 =                                            \
                reinterpret_cast<const ulonglong2*>(&hs[1][PQ][hb[c]]);       \
            const ulonglong2 E = g1[0], F = g1[1], G = g1[2], H = g1[3];      \
            fma2(r0, wc[0][0], E.x);  fma2(r1, wc[1][0], E.x);                \
            fma2(r0, wc[0][1], E.y);  fma2(r1, wc[1][1], E.y);                \
            fma2(r0, wc[0][2], F.x);  fma2(r1, wc[1][2], F.x);                \
            fma2(r0, wc[0][3], F.y);  fma2(r1, wc[1][3], F.y);                \
            fma2(r0, wc[0][4], G.x);  fma2(r1, wc[1][4], G.x);                \
            fma2(r0, wc[0][5], G.y);  fma2(r1, wc[1][5], G.y);                \
            fma2(r0, wc[0][6], H.x);  fma2(r1, wc[1][6], H.x);                \
            fma2(r0, wc[0][7], H.y);  fma2(r1, wc[1][7], H.y);                \
            pp[c] = foldp(r0, r1);                                            \
        }                                                                     \
        {                                                                     \
            u64 v0 = add2(pp[0], shx(pp[1], 4));                              \
            u64 v1 = add2(pp[2], shx(pp[3], 4));                              \
            u64 r  = add2(v0, shx(v1, 8));                                    \
            r = add2(r, bz1);                                                 \
            float f0, f1; unpack2(r, f0, f1);                                 \
            *reinterpret_cast<u64*>(&hs[1][P][sto]) =                         \
                pack2(ftanh(f0), ftanh(f1));                                  \
        }                                                                     \
    }

#pragma unroll 1
    for (int t2 = 0; t2 < TT; t2 += 2) {
        STEP(0, 1, t2)
        __syncthreads();
        STEP(1, 0, t2 + 1)
        __syncthreads();
    }
#undef STEP

    // FC: out[b] = h1(T-1).fcw + fcb ; final parity = 1.
    if (tid < 16) {
        const int swb = tid & 3;
        float sum = fcb[0];
#pragma unroll
        for (int d = 0; d < 16; d++) {
            const float4 hv =
                *reinterpret_cast<const float4*>(&hs[1][1][tid * 64 + d * 4]);
            const float4 wv = reinterpret_cast<const float4*>(fcw)[d ^ swb];
            sum += hv.x * wv.x + hv.y * wv.y + hv.z * wv.z + hv.w * wv.w;
        }
        out[blockIdx.x * 16 + tid] = sum;
    }
}

extern "C" void kernel_launch(void* const* d_in, const int* in_sizes, int n_in,
                              void* d_out, int out_size)
{
    // Inputs: x, W_ih0, W_hh0, b_ih0, b_hh0, W_ih1, W_hh1, b_ih1, b_hh1, fc_w, fc_b
    (void)in_sizes; (void)n_in; (void)out_size;
    rnn_main<<<128, 512>>>(
        (const float*)d_in[0],
        (const float*)d_in[1], (const float*)d_in[2],
        (const float*)d_in[3], (const float*)d_in[4],
        (const float*)d_in[5], (const float*)d_in[6],
        (const float*)d_in[7], (const float*)d_in[8],
        (const float*)d_in[9], (const float*)d_in[10],
        (float*)d_out);
}

// round 13
// speedup vs baseline: 2.5539x; 2.5539x over previous
#include <cuda_runtime.h>
#include <cstddef>

// 2-layer tanh RNN (B=2048,T=512,I=8,H=64)+FC.
// R12: two independent 8-warp groups per block with separate named barriers
// (latency overlap). Group: 8 batches; warp = 8 rows x (2b x 16kg of 4k).
// Weights row-pair-packed in registers (96). k-split-16 distributing
// reduction (R9-validated pattern). Rotation g(B)=4*(B&1) -> conflict-free
// (verified against the 256B-periodic batch stride). Grid 128 = 1 wave.

#define TT 512
typedef unsigned long long u64;

static __device__ __forceinline__ void fma2(u64& a, u64 u, u64 v) {
    asm("fma.rn.f32x2 %0, %1, %2, %0;" : "+l"(a) : "l"(u), "l"(v));
}
static __device__ __forceinline__ u64 mul2(u64 u, u64 v) {
    u64 r; asm("mul.rn.f32x2 %0, %1, %2;" : "=l"(r) : "l"(u), "l"(v)); return r;
}
static __device__ __forceinline__ u64 add2(u64 a, u64 b) {
    u64 r; asm("add.rn.f32x2 %0, %1, %2;" : "=l"(r) : "l"(a), "l"(b)); return r;
}
static __device__ __forceinline__ u64 pack2(float a, float b) {
    u64 r; asm("mov.b64 %0, {%1, %2};" : "=l"(r) : "f"(a), "f"(b)); return r;
}
static __device__ __forceinline__ void unpack2(u64 v, float& a, float& b) {
    asm("mov.b64 {%0, %1}, %2;" : "=f"(a), "=f"(b) : "l"(v));
}
static __device__ __forceinline__ u64 dup2(float a) {
    u64 r; asm("mov.b64 %0, {%1, %1};" : "=l"(r) : "f"(a)); return r;
}
static __device__ __forceinline__ float ftanh(float s) {
    const float e = __expf(2.0f * s);
    return 1.0f - __fdividef(2.0f, e + 1.0f);
}
static __device__ __forceinline__ u64 shx(u64 v, int m) {
    return __shfl_xor_sync(0xffffffffu, v, m, 32);
}
// a[m] += w[m][:] . dup(hq)
static __device__ __forceinline__ void mac4(u64 a[4], const u64 (*w)[4], float4 hq) {
    const u64 d0 = dup2(hq.x), d1 = dup2(hq.y), d2 = dup2(hq.z), d3 = dup2(hq.w);
#pragma unroll
    for (int m = 0; m < 4; m++) {
        fma2(a[m], w[m][0], d0); fma2(a[m], w[m][1], d1);
        fma2(a[m], w[m][2], d2); fma2(a[m], w[m][3], d3);
    }
}
// pair-slot distributing rounds (slots hold pair m ^ (kg&3)); kg bit1->mask4, bit0->mask2
static __device__ __forceinline__ u64 pair_reduce(u64 a[4]) {
    const u64 t0 = add2(a[0], shx(a[2], 4));
    const u64 t1 = add2(a[1], shx(a[3], 4));
    return add2(t0, shx(t1, 2));
}

__global__ void __launch_bounds__(512, 1)
rnn_main(const float* __restrict__ x,
         const float* __restrict__ Wih0, const float* __restrict__ Whh0,
         const float* __restrict__ bi0,  const float* __restrict__ bh0,
         const float* __restrict__ Wih1, const float* __restrict__ Whh1,
         const float* __restrict__ bi1,  const float* __restrict__ bh1,
         const float* __restrict__ fcw,  const float* __restrict__ fcb,
         float* __restrict__ out)
{
    // [group][parity][batch*64 + slot*4 + i], slot = (quad + 4*(B&1)) & 15
    __shared__ __align__(16) float h0s[2][2][512];
    __shared__ __align__(16) float h1s[2][2][512];
    __shared__ __align__(8)  float bsm[2][64];

    const int tid  = threadIdx.x;
    const int gid  = tid >> 8;            // group 0/1
    const int wg   = (tid >> 5) & 7;      // warp in group: rows wg*8..wg*8+7
    const int lane = tid & 31;
    const int b    = lane & 1;            // batch lane
    const int kg   = lane >> 1;           // k-group: k in [4kg, 4kg+4)
    const int lo2  = kg & 3;              // pair-slot perm
    const int hi2  = kg >> 2;             // chunk-slot perm
    const int j0   = wg * 8;
    const int xi   = kg & 7;              // owned x input (kg>=8: zero weights)

    for (int i = tid; i < 1024; i += 512) {
        h0s[i >> 9][1][i & 511] = 0.f;
        h1s[i >> 9][1][i & 511] = 0.f;
    }
    if (tid < 64) {
        bsm[0][tid] = bi0[tid] + bh0[tid];
        bsm[1][tid] = bi1[tid] + bh1[tid];
    }

    // chunk-slot m -> local batch B = (m^hi2)*2 + b
    int off[4], hbo[4];
#pragma unroll
    for (int m = 0; m < 4; m++) {
        const int B = (m ^ hi2) * 2 + b;
        off[m] = B * (TT * 8);
        hbo[m] = B * 64 + ((kg + 4 * b) & 15) * 4;   // quad kg, rotated
    }
    const int Bo  = hi2 * 2 + b;   // owned batch
    const int sto = Bo * 64 + (((wg * 2 + (lo2 >> 1)) + 4 * b) & 15) * 4 + 2 * (lo2 & 1);

    // weights: slot m covers rows jp..jp+1, jp = j0 + 2*(m^lo2); row-pair packed
    u64 wa[4][4], wb_[4][4], wc_[4][4], wxs[4];
#pragma unroll
    for (int m = 0; m < 4; m++) {
        const int jp = j0 + 2 * (m ^ lo2);
#pragma unroll
        for (int kk = 0; kk < 4; kk++) {
            const int k = 4 * kg + kk;
            wa[m][kk]  = pack2(Whh0[jp * 64 + k], Whh0[(jp + 1) * 64 + k]);
            wb_[m][kk] = pack2(Wih1[jp * 64 + k], Wih1[(jp + 1) * 64 + k]);
            wc_[m][kk] = pack2(Whh1[jp * 64 + k], Whh1[(jp + 1) * 64 + k]);
        }
        wxs[m] = (kg < 8) ? pack2(Wih0[jp * 8 + xi], Wih0[(jp + 1) * 8 + xi]) : 0ull;
    }
    const float* xbase = x + (size_t)(blockIdx.x * 16 + gid * 8) * (TT * 8) + xi;

    __syncthreads();
    const int jb = j0 + 2 * lo2;          // owned rows (bias)
    const u64 bz0 = *reinterpret_cast<const u64*>(&bsm[0][jb]);
    const u64 bz1 = *reinterpret_cast<const u64*>(&bsm[1][jb]);
    const int bar = gid + 1;

#pragma unroll 1
    for (int t = 0; t < TT; t++) {
        const int p = t & 1, pq = p ^ 1;
        const float* h0rd = h0s[gid][pq];

        // ---------------- layer 0: Whh0 @ h0(t-1) + Wih0 @ x(t) ----------------
        u64 zA, zB;
        {
            u64 a[4];
            // chunk slot 0
            {
                const u64 xd = dup2(xbase[off[0] + t * 8]);
#pragma unroll
                for (int m = 0; m < 4; m++) a[m] = mul2(wxs[m], xd);
                mac4(a, wa, *reinterpret_cast<const float4*>(&h0rd[hbo[0]]));
                zA = pair_reduce(a);
            }
            // chunk slot 2
            {
                const u64 xd = dup2(xbase[off[2] + t * 8]);
#pragma unroll
                for (int m = 0; m < 4; m++) a[m] = mul2(wxs[m], xd);
                mac4(a, wa, *reinterpret_cast<const float4*>(&h0rd[hbo[2]]));
                zA = add2(zA, shx(pair_reduce(a), 16));
            }
            // chunk slot 1
            {
                const u64 xd = dup2(xbase[off[1] + t * 8]);
#pragma unroll
                for (int m = 0; m < 4; m++) a[m] = mul2(wxs[m], xd);
                mac4(a, wa, *reinterpret_cast<const float4*>(&h0rd[hbo[1]]));
                zB = pair_reduce(a);
            }
            // chunk slot 3
            {
                const u64 xd = dup2(xbase[off[3] + t * 8]);
#pragma unroll
                for (int m = 0; m < 4; m++) a[m] = mul2(wxs[m], xd);
                mac4(a, wa, *reinterpret_cast<const float4*>(&h0rd[hbo[3]]));
                zB = add2(zB, shx(pair_reduce(a), 16));
            }
        }
        {
            u64 r = add2(zA, shx(zB, 8));
            r = add2(r, bz0);
            float f0, f1; unpack2(r, f0, f1);
            *reinterpret_cast<u64*>(&h0s[gid][p][sto]) = pack2(ftanh(f0), ftanh(f1));
        }
        asm volatile("bar.sync %0, %1;" :: "r"(bar), "r"(256) : "memory");

        // ---------- layer 1: Wih1 @ h0(t) + Whh1 @ h1(t-1) ----------
        const float* h0n = h0s[gid][p];
        const float* h1r = h1s[gid][pq];
        {
            u64 a[4];
#pragma unroll
            for (int c = 0; c < 2; c++) {          // slots {0,2} then {1,3}
                const int mA = c, mB = c + 2;
                {
                    const float4 q0 = *reinterpret_cast<const float4*>(&h0n[hbo[mA]]);
                    const u64 d0 = dup2(q0.x), d1 = dup2(q0.y), d2 = dup2(q0.z), d3 = dup2(q0.w);
#pragma unroll
                    for (int m = 0; m < 4; m++) {
                        a[m] = mul2(wb_[m][0], d0); fma2(a[m], wb_[m][1], d1);
                        fma2(a[m], wb_[m][2], d2);  fma2(a[m], wb_[m][3], d3);
                    }
                    mac4(a, wc_, *reinterpret_cast<const float4*>(&h1r[hbo[mA]]));
                    if (c == 0) zA = pair_reduce(a); else zB = pair_reduce(a);
                }
                {
                    const float4 q0 = *reinterpret_cast<const float4*>(&h0n[hbo[mB]]);
                    const u64 d0 = dup2(q0.x), d1 = dup2(q0.y), d2 = dup2(q0.z), d3 = dup2(q0.w);
#pragma unroll
                    for (int m = 0; m < 4; m++) {
                        a[m] = mul2(wb_[m][0], d0); fma2(a[m], wb_[m][1], d1);
                        fma2(a[m], wb_[m][2], d2);  fma2(a[m], wb_[m][3], d3);
                    }
                    mac4(a, wc_, *reinterpret_cast<const float4*>(&h1r[hbo[mB]]));
                    if (c == 0) zA = add2(zA, shx(pair_reduce(a), 16));
                    else        zB = add2(zB, shx(pair_reduce(a), 16));
                }
            }
        }
        {
            u64 r = add2(zA, shx(zB, 8));
            r = add2(r, bz1);
            float f0, f1; unpack2(r, f0, f1);
            *reinterpret_cast<u64*>(&h1s[gid][p][sto]) = pack2(ftanh(f0), ftanh(f1));
        }
        // no trailing barrier: next step's mid barrier orders h1 writes/reads
    }

    __syncthreads();

    // FC: out[b] = h1(T-1) . fcw + fcb ; final parity = 1
    if (tid < 16) {
        const int grp = tid >> 3, lb = tid & 7;
        const int g4  = (lb & 1) * 4;
        float sum = fcb[0];
#pragma unroll
        for (int q = 0; q < 16; q++) {
            const float4 hv = *reinterpret_cast<const float4*>(
                &h1s[grp][1][lb * 64 + (((q + g4) & 15) << 2)]);
            const float4 wv = reinterpret_cast<const float4*>(fcw)[q];
            sum += hv.x * wv.x + hv.y * wv.y + hv.z * wv.z + hv.w * wv.w;
        }
        out[blockIdx.x * 16 + tid] = sum;
    }
}

extern "C" void kernel_launch(void* const* d_in, const int* in_sizes, int n_in,
                              void* d_out, int out_size)
{
    // Inputs: x, W_ih0, W_hh0, b_ih0, b_hh0, W_ih1, W_hh1, b_ih1, b_hh1, fc_w, fc_b
    (void)in_sizes; (void)n_in; (void)out_size;
    rnn_main<<<128, 512>>>(
        (const float*)d_in[0],
        (const float*)d_in[1], (const float*)d_in[2],
        (const float*)d_in[3], (const float*)d_in[4],
        (const float*)d_in[5], (const float*)d_in[6],
        (const float*)d_in[7], (const float*)d_in[8],
        (const float*)d_in[9], (const float*)d_in[10],
        (float*)d_out);
}

// round 14
// speedup vs baseline: 3.4026x; 1.3323x over previous
#include <cuda_runtime.h>
#include <cstddef>

// 2-layer tanh RNN (B=2048,T=512,I=8,H=64)+FC.
// R13 = R7 trunk + x(t+1) register prefetch + 7-shuffle streaming reduction
// (R10-validated slot math, zA/zB streaming so no vv[4]) + biases via
// non-hoistable LDS.128. Weights in registers (96), rotated conflict-free h
// layout, 1 barrier/step, grid 128 = 1 wave.

#define TT 512
typedef unsigned long long u64;

static __device__ __forceinline__ void fma2(u64& a, u64 u, u64 v) {
    asm("fma.rn.f32x2 %0, %1, %2, %0;" : "+l"(a) : "l"(u), "l"(v));
}
static __device__ __forceinline__ u64 mul2(u64 u, u64 v) {
    u64 r; asm("mul.rn.f32x2 %0, %1, %2;" : "=l"(r) : "l"(u), "l"(v)); return r;
}
static __device__ __forceinline__ u64 add2(u64 a, u64 b) {
    u64 r; asm("add.rn.f32x2 %0, %1, %2;" : "=l"(r) : "l"(a), "l"(b)); return r;
}
static __device__ __forceinline__ u64 pack2(float a, float b) {
    u64 r; asm("mov.b64 %0, {%1, %2};" : "=l"(r) : "f"(a), "f"(b)); return r;
}
static __device__ __forceinline__ void unpack2(u64 v, float& a, float& b) {
    asm("mov.b64 {%0, %1}, %2;" : "=f"(a), "=f"(b) : "l"(v));
}
static __device__ __forceinline__ u64 dup2(float a) {
    u64 r; asm("mov.b64 %0, {%1, %1};" : "=l"(r) : "f"(a)); return r;
}
static __device__ __forceinline__ float ftanh(float s) {
    const float e = __expf(2.0f * s);
    return 1.0f - __fdividef(2.0f, e + 1.0f);
}
static __device__ __forceinline__ u64 shx(u64 v, int m) {
    return __shfl_xor_sync(0xffffffffu, v, m, 32);
}
static __device__ __forceinline__ u64 foldp(u64 a, u64 b) {
    float l0, m0, l1, m1;
    unpack2(a, l0, m0); unpack2(b, l1, m1);
    return pack2(l0 + m0, l1 + m1);
}
static __device__ __forceinline__ unsigned smem_u32(const void* p) {
    unsigned a;
    asm("{ .reg .u64 t; cvta.to.shared.u64 t, %1; cvt.u32.u64 %0, t; }"
        : "=r"(a) : "l"(p));
    return a;
}

__global__ void __launch_bounds__(512, 1)
rnn_main(const float* __restrict__ x,
         const float* __restrict__ Wih0, const float* __restrict__ Whh0,
         const float* __restrict__ bi0,  const float* __restrict__ bh0,
         const float* __restrict__ Wih1, const float* __restrict__ Whh1,
         const float* __restrict__ bi1,  const float* __restrict__ bh1,
         const float* __restrict__ fcw,  const float* __restrict__ fcb,
         float* __restrict__ out)
{
    __shared__ __align__(16) float h0s[2][16 * 64];
    __shared__ __align__(16) float h1s[2][16 * 64];
    __shared__ __align__(16) float ibs[128];   // [pair m][b0_lo,b0_hi,b1_lo,b1_hi]

    const int tid  = threadIdx.x;
    const int lane = tid & 31;
    const int w    = tid >> 5;               // rows j0..j0+3
    const int b    = lane & 3;
    const int kg   = lane >> 2;              // k in [8kg, 8kg+8)
    const int s    = kg & 1;                 // owned row-pair
    const int p2   = (((kg >> 1) & 1) << 1) | ((kg >> 2) & 1);  // owned chunk
    const int j0   = w * 4;
    const int g    = (b & 1) | ((b & 2) << 1);

    for (int i = tid; i < 16 * 64; i += 512) { h0s[1][i] = 0.f; h1s[1][i] = 0.f; }
    if (tid < 64) {
        const int m = tid >> 1, r = tid & 1;
        ibs[m * 4 + r]     = bi0[tid] + bh0[tid];
        ibs[m * 4 + 2 + r] = bi1[tid] + bh1[tid];
    }

    // Per-chunk-slot offsets (chunk(slot c) = c ^ p2; batch = chunk*4 + b).
    int ofA[4], ofB[4], xof[4];
#pragma unroll
    for (int c = 0; c < 4; c++) {
        const int B = (c ^ p2) * 4 + b;
        ofA[c] = B * 64 + (((2 * kg     + g) & 15) << 2);
        ofB[c] = B * 64 + (((2 * kg + 1 + g) & 15) << 2);
        xof[c] = (blockIdx.x * 16 + B) * (TT * 8) + kg;
    }
    const int sto = (p2 * 4 + b) * 64 + (((w + g) & 15) << 2) + 2 * s;
    const unsigned baddr = smem_u32(&ibs[(w * 2 + s) * 4]);

    // Weights in registers; row slot q covers physical row-pair (q^s).
    u64 wa[2][2][4], wb[2][2][4], wc[2][2][4], wxp[2];
#pragma unroll
    for (int q = 0; q < 2; q++) {
        const int jA = j0 + 2 * (q ^ s);
#pragma unroll
        for (int h = 0; h < 2; h++) {
            const int base = ((jA + h) * 64 + kg * 8) >> 1;
#pragma unroll
            for (int kk = 0; kk < 4; kk++) {
                wa[q][h][kk] = reinterpret_cast<const u64*>(Whh0)[base + kk];
                wb[q][h][kk] = reinterpret_cast<const u64*>(Wih1)[base + kk];
                wc[q][h][kk] = reinterpret_cast<const u64*>(Whh1)[base + kk];
            }
        }
        wxp[q] = pack2(Wih0[jA * 8 + kg], Wih0[(jA + 1) * 8 + kg]);
    }

    float xv[4];
#pragma unroll
    for (int c = 0; c < 4; c++) xv[c] = x[xof[c]];   // t = 0

    __syncthreads();

// layer-0 chunk slot: acc over Whh0 + x-term, round A (xor4) -> dst
#define L0SLOT(c, dst)                                                        \
    {                                                                         \
        const u64* qa = reinterpret_cast<const u64*>(&h0s[pq][ofA[c]]);       \
        const u64* qb = reinterpret_cast<const u64*>(&h0s[pq][ofB[c]]);       \
        const u64 u0 = qa[0], u1 = qa[1], u2 = qb[0], u3 = qb[1];             \
        u64 a00 = mul2(wa[0][0][0], u0), a01 = mul2(wa[0][1][0], u0);         \
        u64 a10 = mul2(wa[1][0][0], u0), a11 = mul2(wa[1][1][0], u0);         \
        fma2(a00, wa[0][0][1], u1); fma2(a01, wa[0][1][1], u1);               \
        fma2(a10, wa[1][0][1], u1); fma2(a11, wa[1][1][1], u1);               \
        fma2(a00, wa[0][0][2], u2); fma2(a01, wa[0][1][2], u2);               \
        fma2(a10, wa[1][0][2], u2); fma2(a11, wa[1][1][2], u2);               \
        fma2(a00, wa[0][0][3], u3); fma2(a01, wa[0][1][3], u3);               \
        fma2(a10, wa[1][0][3], u3); fma2(a11, wa[1][1][3], u3);               \
        u64 p0 = foldp(a00, a01);                                             \
        u64 p1 = foldp(a10, a11);                                             \
        const u64 xd = dup2(xv[c]);                                           \
        fma2(p0, wxp[0], xd);                                                 \
        fma2(p1, wxp[1], xd);                                                 \
        dst = add2(p0, shx(p1, 4));                                           \
    }

// layer-1 chunk slot: Wih1 @ h0(t) + Whh1 @ h1(t-1), round A -> dst
#define L1SLOT(c, dst)                                                        \
    {                                                                         \
        const u64* qa0 = reinterpret_cast<const u64*>(&h0s[p][ofA[c]]);       \
        const u64* qb0 = reinterpret_cast<const u64*>(&h0s[p][ofB[c]]);       \
        const u64 u0 = qa0[0], u1 = qa0[1], u2 = qb0[0], u3 = qb0[1];         \
        u64 a00 = mul2(wb[0][0][0], u0), a01 = mul2(wb[0][1][0], u0);         \
        u64 a10 = mul2(wb[1][0][0], u0), a11 = mul2(wb[1][1][0], u0);         \
        fma2(a00, wb[0][0][1], u1); fma2(a01, wb[0][1][1], u1);               \
        fma2(a10, wb[1][0][1], u1); fma2(a11, wb[1][1][1], u1);               \
        fma2(a00, wb[0][0][2], u2); fma2(a01, wb[0][1][2], u2);               \
        fma2(a10, wb[1][0][2], u2); fma2(a11, wb[1][1][2], u2);               \
        fma2(a00, wb[0][0][3], u3); fma2(a01, wb[0][1][3], u3);               \
        fma2(a10, wb[1][0][3], u3); fma2(a11, wb[1][1][3], u3);               \
        const u64* qa1 = reinterpret_cast<const u64*>(&h1s[pq][ofA[c]]);      \
        const u64* qb1 = reinterpret_cast<const u64*>(&h1s[pq][ofB[c]]);      \
        const u64 z0 = qa1[0], z1 = qa1[1], z2 = qb1[0], z3 = qb1[1];         \
        fma2(a00, wc[0][0][0], z0); fma2(a01, wc[0][1][0], z0);               \
        fma2(a10, wc[1][0][0], z0); fma2(a11, wc[1][1][0], z0);               \
        fma2(a00, wc[0][0][1], z1); fma2(a01, wc[0][1][1], z1);               \
        fma2(a10, wc[1][0][1], z1); fma2(a11, wc[1][1][1], z1);               \
        fma2(a00, wc[0][0][2], z2); fma2(a01, wc[0][1][2], z2);               \
        fma2(a10, wc[1][0][2], z2); fma2(a11, wc[1][1][2], z2);               \
        fma2(a00, wc[0][0][3], z3); fma2(a01, wc[0][1][3], z3);               \
        fma2(a10, wc[1][0][3], z3); fma2(a11, wc[1][1][3], z3);               \
        u64 p0 = foldp(a00, a01);                                             \
        u64 p1 = foldp(a10, a11);                                             \
        dst = add2(p0, shx(p1, 4));                                           \
    }

#pragma unroll 1
    for (int t = 0; t < TT; t++) {
        const int p = t & 1, pq = p ^ 1;

        // per-step bias load (asm: not hoistable -> no persistent regs)
        float b00, b01, b10, b11;
        asm volatile("ld.shared.v4.f32 {%0,%1,%2,%3}, [%4];"
                     : "=f"(b00), "=f"(b01), "=f"(b10), "=f"(b11)
                     : "r"(baddr));

        // ---------------- layer 0 ----------------
        {
            u64 s0, s1, s2, s3;
            L0SLOT(0, s0) L0SLOT(2, s2)
            const u64 zA = add2(s0, shx(s2, 8));
            L0SLOT(1, s1) L0SLOT(3, s3)
            const u64 zB = add2(s1, shx(s3, 8));
            const u64 r  = add2(zA, shx(zB, 16));
            float f0, f1; unpack2(r, f0, f1);
            *reinterpret_cast<u64*>(&h0s[p][sto]) =
                pack2(ftanh(f0 + b00), ftanh(f1 + b01));
        }
        __syncthreads();                       // the ONE barrier per step

        // ---------------- layer 1 (+ x prefetch for t+1) ----------------
        const int tn = (t + 1) & (TT - 1);     // wrap: value unused at t=TT-1
        float xn0 = x[xof[0] + tn * 8], xn1 = x[xof[1] + tn * 8];
        float xn2 = x[xof[2] + tn * 8], xn3 = x[xof[3] + tn * 8];
        {
            u64 s0, s1, s2, s3;
            L1SLOT(0, s0) L1SLOT(2, s2)
            const u64 zA = add2(s0, shx(s2, 8));
            L1SLOT(1, s1) L1SLOT(3, s3)
            const u64 zB = add2(s1, shx(s3, 8));
            const u64 r  = add2(zA, shx(zB, 16));
            float f0, f1; unpack2(r, f0, f1);
            *reinterpret_cast<u64*>(&h1s[p][sto]) =
                pack2(ftanh(f0 + b10), ftanh(f1 + b11));
        }
        xv[0] = xn0; xv[1] = xn1; xv[2] = xn2; xv[3] = xn3;
        // no trailing barrier: next step's mid barrier orders h1 writes/reads
    }
#undef L0SLOT
#undef L1SLOT

    __syncthreads();

    // FC: out[b] = h1(T-1) . fcw + fcb ; final parity = (TT-1)&1 = 1
    if (tid < 16) {
        const int gg = (tid & 1) | ((tid & 2) << 1);
        float sum = fcb[0];
#pragma unroll
        for (int q = 0; q < 16; q++) {
            const float4 hv = *reinterpret_cast<const float4*>(
                &h1s[1][tid * 64 + (((q + gg) & 15) << 2)]);
            const float4 wv = reinterpret_cast<const float4*>(fcw)[q];
            sum += hv.x * wv.x + hv.y * wv.y + hv.z * wv.z + hv.w * wv.w;
        }
        out[blockIdx.x * 16 + tid] = sum;
    }
}

extern "C" void kernel_launch(void* const* d_in, const int* in_sizes, int n_in,
                              void* d_out, int out_size)
{
    // Inputs: x, W_ih0, W_hh0, b_ih0, b_hh0, W_ih1, W_hh1, b_ih1, b_hh1, fc_w, fc_b
    (void)in_sizes; (void)n_in; (void)out_size;
    rnn_main<<<128, 512>>>(
        (const float*)d_in[0],
        (const float*)d_in[1], (const float*)d_in[2],
        (const float*)d_in[3], (const float*)d_in[4],
        (const float*)d_in[5], (const float*)d_in[6],
        (const float*)d_in[7], (const float*)d_in[8],
        (const float*)d_in[9], (const float*)d_in[10],
        (float*)d_out);
}

// round 16
// speedup vs baseline: 3.8990x; 1.1459x over previous
#include <cuda_runtime.h>
#include <cstddef>

// 2-layer tanh RNN (B=2048,T=512,I=8,H=64)+FC.
// R14 = R7 (best: 971.5us) + ONE change: x(t+1) prefetched into registers at
// the start of layer-1 (register-neutral: xn's live range fills xv's dead
// range). Everything else byte-identical to R7: weight-stationary registers,
// k-split-8, conflict-free rotated h layout, 1 barrier/step, grid 128 = 1 wave.

#define TT 512
typedef unsigned long long u64;

static __device__ __forceinline__ void fma2(u64& a, u64 u, u64 v) {
    asm("fma.rn.f32x2 %0, %1, %2, %0;" : "+l"(a) : "l"(u), "l"(v));
}
static __device__ __forceinline__ u64 mul2(u64 u, u64 v) {
    u64 r; asm("mul.rn.f32x2 %0, %1, %2;" : "=l"(r) : "l"(u), "l"(v)); return r;
}
static __device__ __forceinline__ u64 add2(u64 a, u64 b) {
    u64 r; asm("add.rn.f32x2 %0, %1, %2;" : "=l"(r) : "l"(a), "l"(b)); return r;
}
static __device__ __forceinline__ u64 pack2(float a, float b) {
    u64 r; asm("mov.b64 %0, {%1, %2};" : "=l"(r) : "f"(a), "f"(b)); return r;
}
static __device__ __forceinline__ void unpack2(u64 v, float& a, float& b) {
    asm("mov.b64 {%0, %1}, %2;" : "=f"(a), "=f"(b) : "l"(v));
}
static __device__ __forceinline__ u64 dup2(float a) {
    u64 r; asm("mov.b64 %0, {%1, %1};" : "=l"(r) : "f"(a)); return r;
}
static __device__ __forceinline__ float ftanh(float s) {
    const float e = __expf(2.0f * s);
    return 1.0f - __fdividef(2.0f, e + 1.0f);
}
static __device__ __forceinline__ u64 shx(u64 v, int m) {
    return __shfl_xor_sync(0xffffffffu, v, m, 32);
}
static __device__ __forceinline__ u64 foldp(u64 a, u64 b) {
    float l0, m0, l1, m1;
    unpack2(a, l0, m0); unpack2(b, l1, m1);
    return pack2(l0 + m0, l1 + m1);
}

__global__ void __launch_bounds__(512, 1)
rnn_main(const float* __restrict__ x,
         const float* __restrict__ Wih0, const float* __restrict__ Whh0,
         const float* __restrict__ bi0,  const float* __restrict__ bh0,
         const float* __restrict__ Wih1, const float* __restrict__ Whh1,
         const float* __restrict__ bi1,  const float* __restrict__ bh1,
         const float* __restrict__ fcw,  const float* __restrict__ fcb,
         float* __restrict__ out)
{
    // h: [parity][batch 0..15][quad-slot 0..15] float4s; quad q of batch B
    // lives at slot (q + g(B)) & 15, g(B) = (B&1)|((B&2)<<1).
    __shared__ __align__(16) float h0s[2][16 * 64];
    __shared__ __align__(16) float h1s[2][16 * 64];

    const int tid  = threadIdx.x;
    const int lane = tid & 31;
    const int w    = tid >> 5;      // 16 warps -> rows j0..j0+3
    const int b    = lane & 3;      // batch lane (B mod 4 == b)
    const int kg   = lane >> 2;     // k-group: k in [8kg, 8kg+8)
    const int s    = kg & 1;        // slot-permute bit (owned row-pair = s)
    const int j0   = w * 4;
    const int g    = (b & 1) | ((b & 2) << 1);   // quad rotation for this b

    for (int i = tid; i < 16 * 64; i += 512) { h0s[1][i] = 0.f; h1s[1][i] = 0.f; }

    // Precomputed conflict-free read offsets (floats): chunk bi, quads 2kg,2kg+1
    int ofA[4], ofB[4], xof[4];
#pragma unroll
    for (int bi = 0; bi < 4; bi++) {
        const int B = bi * 4 + b;
        ofA[bi] = B * 64 + (((2 * kg     + g) & 15) << 2);
        ofB[bi] = B * 64 + (((2 * kg + 1 + g) & 15) << 2);
        xof[bi] = (blockIdx.x * 16 + B) * (TT * 8) + kg;
    }
    // Owned store offset: batch Bm = mychunk*4+b, rows j0+2s
    const int mychunk = kg >> 1;
    const int sto = (mychunk * 4 + b) * 64 + (((w + g) & 15) << 2) + 2 * s;

    // Weights in registers; acc slot q covers physical row-pair (q^s).
    u64 wa[2][2][4], wb[2][2][4], wc[2][2][4], wxp[2];
#pragma unroll
    for (int q = 0; q < 2; q++) {
        const int jA = j0 + 2 * (q ^ s);
#pragma unroll
        for (int h = 0; h < 2; h++) {
            const int base = ((jA + h) * 64 + kg * 8) >> 1;   // u64 index
#pragma unroll
            for (int kk = 0; kk < 4; kk++) {
                wa[q][h][kk] = reinterpret_cast<const u64*>(Whh0)[base + kk];
                wb[q][h][kk] = reinterpret_cast<const u64*>(Wih1)[base + kk];
                wc[q][h][kk] = reinterpret_cast<const u64*>(Whh1)[base + kk];
            }
        }
        wxp[q] = pack2(Wih0[jA * 8 + kg], Wih0[(jA + 1) * 8 + kg]);
    }
    const u64 bz0 = pack2(bi0[j0+2*s] + bh0[j0+2*s], bi0[j0+2*s+1] + bh0[j0+2*s+1]);
    const u64 bz1 = pack2(bi1[j0+2*s] + bh1[j0+2*s], bi1[j0+2*s+1] + bh1[j0+2*s+1]);

    float xv[4];
#pragma unroll
    for (int bi = 0; bi < 4; bi++) xv[bi] = x[xof[bi]];   // t = 0

    __syncthreads();

#pragma unroll 1
    for (int t = 0; t < TT; t++) {
        const int p = t & 1, pp = p ^ 1;

        // ---------------- layer 0: Whh0 @ h0_prev + Wih0 @ x ----------------
        u64 vv[4];
#pragma unroll
        for (int bi = 0; bi < 4; bi++) {
            const u64* qa = reinterpret_cast<const u64*>(&h0s[pp][ofA[bi]]);
            const u64* qb = reinterpret_cast<const u64*>(&h0s[pp][ofB[bi]]);
            const u64 h0 = qa[0], h1 = qa[1], h2 = qb[0], h3 = qb[1];
            u64 a[2][2];
#pragma unroll
            for (int q = 0; q < 2; q++)
#pragma unroll
                for (int h = 0; h < 2; h++) {
                    a[q][h] = mul2(wa[q][h][0], h0);
                    fma2(a[q][h], wa[q][h][1], h1);
                    fma2(a[q][h], wa[q][h][2], h2);
                    fma2(a[q][h], wa[q][h][3], h3);
                }
            u64 v[2];
            const u64 xd = dup2(xv[bi]);
#pragma unroll
            for (int q = 0; q < 2; q++) {
                float l0, m0, l1, m1;
                unpack2(a[q][0], l0, m0); unpack2(a[q][1], l1, m1);
                v[q] = pack2(l0 + m0, l1 + m1);
                fma2(v[q], wxp[q], xd);
            }
            u64 r = add2(v[0], shx(v[1], 4));
            r = add2(r, shx(r, 8));
            r = add2(r, shx(r, 16));
            if (mychunk == bi) vv[0] = r;     // keep (other slots reused below)
            if (bi == 0) vv[1] = r;           // dead placeholder keeps ptxas calm
        }
        {
            u64 keep0 = add2(vv[0], bz0);
            float f0, f1;
            unpack2(keep0, f0, f1);
            *reinterpret_cast<u64*>(&h0s[p][sto]) = pack2(ftanh(f0), ftanh(f1));
        }
        __syncthreads();   // single per-step barrier

        // -------- x prefetch for t+1 (xv dead here: register-neutral) --------
        const int tn = (t + 1) & (TT - 1);    // wrap at end; value unused
        float xn0 = x[xof[0] + tn * 8];
        float xn1 = x[xof[1] + tn * 8];
        float xn2 = x[xof[2] + tn * 8];
        float xn3 = x[xof[3] + tn * 8];

        // ---------- layer 1: Wih1 @ h0_new + Whh1 @ h1_prev ----------
        u64 keep1;
#pragma unroll
        for (int bi = 0; bi < 4; bi++) {
            const u64* qa0 = reinterpret_cast<const u64*>(&h0s[p][ofA[bi]]);
            const u64* qb0 = reinterpret_cast<const u64*>(&h0s[p][ofB[bi]]);
            const u64 u0 = qa0[0], u1 = qa0[1], u2 = qb0[0], u3 = qb0[1];
            u64 a[2][2];
#pragma unroll
            for (int q = 0; q < 2; q++)
#pragma unroll
                for (int h = 0; h < 2; h++) {
                    a[q][h] = mul2(wb[q][h][0], u0);
                    fma2(a[q][h], wb[q][h][1], u1);
                    fma2(a[q][h], wb[q][h][2], u2);
                    fma2(a[q][h], wb[q][h][3], u3);
                }
            const u64* qa1 = reinterpret_cast<const u64*>(&h1s[pp][ofA[bi]]);
            const u64* qb1 = reinterpret_cast<const u64*>(&h1s[pp][ofB[bi]]);
            const u64 z0 = qa1[0], z1 = qa1[1], z2 = qb1[0], z3 = qb1[1];
#pragma unroll
            for (int q = 0; q < 2; q++)
#pragma unroll
                for (int h = 0; h < 2; h++) {
                    fma2(a[q][h], wc[q][h][0], z0);
                    fma2(a[q][h], wc[q][h][1], z1);
                    fma2(a[q][h], wc[q][h][2], z2);
                    fma2(a[q][h], wc[q][h][3], z3);
                }
            u64 v[2];
#pragma unroll
            for (int q = 0; q < 2; q++) {
                float l0, m0, l1, m1;
                unpack2(a[q][0], l0, m0); unpack2(a[q][1], l1, m1);
                v[q] = pack2(l0 + m0, l1 + m1);
            }
            u64 r = add2(v[0], shx(v[1], 4));
            r = add2(r, shx(r, 8));
            r = add2(r, shx(r, 16));
            if (mychunk == bi) keep1 = r;
        }
        {
            keep1 = add2(keep1, bz1);
            float f0, f1;
            unpack2(keep1, f0, f1);
            *reinterpret_cast<u64*>(&h1s[p][sto]) = pack2(ftanh(f0), ftanh(f1));
        }
        xv[0] = xn0; xv[1] = xn1; xv[2] = xn2; xv[3] = xn3;
        // next step's mid barrier orders this step's h1 writes vs its reads
    }

    __syncthreads();

    // FC: out[b] = h1(T-1) . fcw + fcb ; final parity = (TT-1)&1 = 1
    if (tid < 16) {
        const int gg = (tid & 1) | ((tid & 2) << 1);
        float sum = fcb[0];
#pragma unroll
        for (int q = 0; q < 16; q++) {
            const float4 hv = *reinterpret_cast<const float4*>(
                &h1s[1][tid * 64 + (((q + gg) & 15) << 2)]);
            const float4 wv = reinterpret_cast<const float4*>(fcw)[q];
            sum += hv.x * wv.x + hv.y * wv.y + hv.z * wv.z + hv.w * wv.w;
        }
        out[blockIdx.x * 16 + tid] = sum;
    }
}

extern "C" void kernel_launch(void* const* d_in, const int* in_sizes, int n_in,
                              void* d_out, int out_size)
{
    // Inputs: x, W_ih0, W_hh0, b_ih0, b_hh0, W_ih1, W_hh1, b_ih1, b_hh1, fc_w, fc_b
    (void)in_sizes; (void)n_in; (void)out_size;
    rnn_main<<<128, 512>>>(
        (const float*)d_in[0],
        (const float*)d_in[1], (const float*)d_in[2],
        (const float*)d_in[3], (const float*)d_in[4],
        (const float*)d_in[5], (const float*)d_in[6],
        (const float*)d_in[7], (const float*)d_in[8],
        (const float*)d_in[9], (const float*)d_in[10],
        (float*)d_out);
}